// round 2
// baseline (speedup 1.0000x reference)
#include <cuda_runtime.h>
#include <cuda_bf16.h>
#include <math.h>
#include <stdint.h>

#define BBATCH 64
#define LLEN 128
#define TSTEPS 48
#define EDIM 512
#define HEDIM 1024
#define HDIM 1024

typedef __nv_bfloat16 bf16;

// ---------------- device scratch (no allocations allowed) ----------------
__device__ bf16 g_Wih1[4096 * 1024];      // [4096][2*512]   hi|lo, gate-interleaved rows
__device__ bf16 g_Whh1[4096 * 2048];      // [4096][2*1024]
__device__ bf16 g_Wih2A[4096 * 2048];     // W_ih2 cols 0..1023
__device__ bf16 g_Wih2B[4096 * 2048];     // W_ih2 cols 1024..2047
__device__ bf16 g_Whh2[4096 * 2048];
__device__ bf16 g_WcmA[1024 * 2048];      // W_comb cols 0..1023 (a_t part)
__device__ bf16 g_WcmB[1024 * 2048];      // W_comb cols 1024..2047 (h2 part)
__device__ bf16 g_Watt[1024 * 2048];
__device__ bf16 g_enchl[8192 * 2048];     // enc_hiddens hi|lo
__device__ bf16 g_capshl[3072 * 1024];    // captions hi|lo  (48*64 rows, 2*512 cols)
__device__ float g_encproj[8192 * 1024];  // fp32 enc projection
__device__ bf16 g_h1hl[2][BBATCH * 2048];
__device__ bf16 g_h2hl[2][BBATCH * 2048];
__device__ bf16 g_ohl[BBATCH * 2048];
__device__ bf16 g_athl[BBATCH * 2048];
__device__ float g_c1[BBATCH * HDIM];
__device__ float g_c2[BBATCH * HDIM];
__device__ float g_h2f[BBATCH * HDIM];
__device__ float g_bg1[4096];
__device__ float g_bg2[4096];

// ---------------- helpers ----------------
__device__ __forceinline__ float sigm(float x) { return 1.f / (1.f + __expf(-x)); }

#define CP16(dst, src) \
    asm volatile("cp.async.cg.shared.global [%0], [%1], 16;\n" ::"r"(dst), "l"(src))
#define LDSM4(R0, R1, R2, R3, ADDR)                                        \
    asm volatile("ldmatrix.sync.aligned.m8n8.x4.shared.b16 {%0,%1,%2,%3},[%4];\n" \
                 : "=r"(R0), "=r"(R1), "=r"(R2), "=r"(R3)                  \
                 : "r"(ADDR))
#define MMA16816(C, A0, A1, A2, A3, B0, B1)                                    \
    asm volatile(                                                               \
        "mma.sync.aligned.m16n8k16.row.col.f32.bf16.bf16.f32 "                  \
        "{%0,%1,%2,%3},{%4,%5,%6,%7},{%8,%9},{%0,%1,%2,%3};\n"                  \
        : "+f"((C)[0]), "+f"((C)[1]), "+f"((C)[2]), "+f"((C)[3])                \
        : "r"(A0), "r"(A1), "r"(A2), "r"(A3), "r"(B0), "r"(B1))

// ---------------- conversion: fp32 -> [hi|lo] bf16 ----------------
__global__ void conv_whl(const float* __restrict__ src, int srcld, int colOff, int K,
                         bf16* __restrict__ dst, int interleave, int N) {
    int idx = blockIdx.x * 256 + threadIdx.x;
    if (idx >= N * K) return;
    int n = idx / K, k = idx - n * K;
    int srcn = interleave ? ((n & 3) * HDIM + (n >> 2)) : n;
    float v = src[(size_t)srcn * srcld + colOff + k];
    bf16 hi = __float2bfloat16(v);
    bf16 lo = __float2bfloat16(v - __bfloat162float(hi));
    dst[(size_t)n * 2 * K + k] = hi;
    dst[(size_t)n * 2 * K + K + k] = lo;
}

__global__ void conv_bias(const float* __restrict__ bi1, const float* __restrict__ bh1,
                          const float* __restrict__ bi2, const float* __restrict__ bh2) {
    int n = blockIdx.x * 256 + threadIdx.x;
    if (n >= 4096) return;
    int srcn = (n & 3) * HDIM + (n >> 2);
    g_bg1[n] = bi1[srcn] + bh1[srcn];
    g_bg2[n] = bi2[srcn] + bh2[srcn];
}

__global__ void init_k(const float* __restrict__ h1i, const float* __restrict__ c1i,
                       const float* __restrict__ h2i, const float* __restrict__ c2i) {
    int i = blockIdx.x * 256 + threadIdx.x;
    if (i >= BBATCH * HDIM) return;
    int b = i >> 10, k = i & 1023;
    g_c1[i] = c1i[i];
    g_c2[i] = c2i[i];
    g_h2f[i] = h2i[i];
    float v1 = h1i[i];
    bf16 h = __float2bfloat16(v1);
    bf16 l = __float2bfloat16(v1 - __bfloat162float(h));
    g_h1hl[0][b * 2048 + k] = h;
    g_h1hl[0][b * 2048 + 1024 + k] = l;
    float v2 = h2i[i];
    h = __float2bfloat16(v2);
    l = __float2bfloat16(v2 - __bfloat162float(h));
    g_h2hl[0][b * 2048 + k] = h;
    g_h2hl[0][b * 2048 + 1024 + k] = l;
    bf16 z = __float2bfloat16(0.f);
    g_ohl[b * 2048 + k] = z;
    g_ohl[b * 2048 + 1024 + k] = z;
}

// ---------------- tensor-core GEMM: C[M64,N32tile] = sum_p 3-seg(A_p @ W_p^T) ----------------
// A_p stored [rows][2*Kp] as hi|lo; W_p stored [N][2*Kp] as hi|lo.
// Segments: (Ahi,Whi), (Ahi,Wlo), (Alo,Whi) -> ~fp32 precision.
// mode 0: store fp32 + bias (enc_proj).  mode 1: LSTM epilogue.  mode 2: tanh epilogue.
#define ASTG 8192   // bytes per A stage (64 x 64 bf16)
#define WSTG 4096   // bytes per W stage (32 x 64 bf16)

__global__ __launch_bounds__(128) void mma_gemm(
    const bf16* A0, const bf16* W0, int K0,
    const bf16* A1, const bf16* W1, int K1,
    const bf16* A2, const bf16* W2, int K2,
    int npairs,
    const float* __restrict__ bias,
    float* __restrict__ outF, int ldo,
    bf16* __restrict__ outHL,
    float* __restrict__ cstate,
    int mode) {
    __shared__ __align__(16) bf16 smemA[2 * 64 * 64];
    __shared__ __align__(16) bf16 smemW[2 * 32 * 64];

    const int tid = threadIdx.x;
    const int w = tid >> 5;
    const int l = tid & 31;
    const int m0 = blockIdx.y * 64;
    const int n0 = blockIdx.x * 32;

    const bf16* Ab[3] = {A0, A1, A2};
    const bf16* Wb[3] = {W0, W1, W2};
    const int Kp[3] = {K0, K1, K2};

    int NIT = 0;
    for (int p = 0; p < npairs; ++p) NIT += 3 * (Kp[p] >> 6);

    const uint32_t asB = (uint32_t)__cvta_generic_to_shared(smemA);
    const uint32_t wsB = (uint32_t)__cvta_generic_to_shared(smemW);

    int cp = 0, cs = 0, ckt = 0;

    auto issue = [&](int stg) {
        const bf16* gA = Ab[cp] + (cs == 2 ? Kp[cp] : 0);
        const bf16* gW = Wb[cp] + (cs == 1 ? Kp[cp] : 0);
        const int ld = Kp[cp] << 1;
        const uint32_t aD = asB + stg * ASTG;
        const uint32_t wD = wsB + stg * WSTG;
#pragma unroll
        for (int i = 0; i < 6; ++i) {
            int c = tid + (i << 7);
            if (c < 512) {
                int row = c >> 3, ch = c & 7;
                const bf16* src = gA + (size_t)(m0 + row) * ld + ckt + (ch << 3);
                uint32_t dst = aD + row * 128 + ((ch ^ (row & 7)) << 4);
                CP16(dst, src);
            } else {
                int c2 = c - 512;
                int row = c2 >> 3, ch = c2 & 7;
                const bf16* src = gW + (size_t)(n0 + row) * ld + ckt + (ch << 3);
                uint32_t dst = wD + row * 128 + ((ch ^ (row & 7)) << 4);
                CP16(dst, src);
            }
        }
        asm volatile("cp.async.commit_group;\n" ::);
        ckt += 64;
        if (ckt >= Kp[cp]) {
            ckt = 0;
            if (++cs == 3) { cs = 0; ++cp; }
        }
    };

    float acc[4][4];
#pragma unroll
    for (int j = 0; j < 4; ++j)
#pragma unroll
        for (int i = 0; i < 4; ++i) acc[j][i] = 0.f;

    issue(0);

    const int arow = 16 * w + (l & 15);
    const int asel = (l >> 4) & 1;           // A k-half select within chunk pair
    const int nrow0 = (l & 7) + ((l & 16) >> 1);
    const int nrow1 = nrow0 + 16;
    const int bsel = (l >> 3) & 1;

    for (int it = 0; it < NIT; ++it) {
        if (it + 1 < NIT) {
            issue((it + 1) & 1);
            asm volatile("cp.async.wait_group 1;\n" ::);
        } else {
            asm volatile("cp.async.wait_group 0;\n" ::);
        }
        __syncthreads();
        const int stg = it & 1;
        const uint32_t aBase = asB + stg * ASTG;
        const uint32_t wBase = wsB + stg * WSTG;
#pragma unroll
        for (int kh = 0; kh < 4; ++kh) {
            int achunk = 2 * kh + asel;
            uint32_t aaddr = aBase + arow * 128 + ((achunk ^ (arow & 7)) << 4);
            uint32_t a0, a1, a2, a3;
            LDSM4(a0, a1, a2, a3, aaddr);
            int bchunk = 2 * kh + bsel;
            uint32_t baddr0 = wBase + nrow0 * 128 + ((bchunk ^ (nrow0 & 7)) << 4);
            uint32_t baddr1 = wBase + nrow1 * 128 + ((bchunk ^ (nrow1 & 7)) << 4);
            uint32_t b0, b1, b2, b3, b4, b5, b6, b7;
            LDSM4(b0, b1, b2, b3, baddr0);
            LDSM4(b4, b5, b6, b7, baddr1);
            MMA16816(acc[0], a0, a1, a2, a3, b0, b1);
            MMA16816(acc[1], a0, a1, a2, a3, b2, b3);
            MMA16816(acc[2], a0, a1, a2, a3, b4, b5);
            MMA16816(acc[3], a0, a1, a2, a3, b6, b7);
        }
        __syncthreads();
    }

    const int r = l >> 2;
    const int c2 = (l & 3) * 2;

    if (mode == 0) {
#pragma unroll
        for (int j = 0; j < 4; ++j) {
            int n = n0 + 8 * j + c2;
            float bv0 = bias[n], bv1 = bias[n + 1];
            size_t row0 = (size_t)(m0 + 16 * w + r);
            outF[row0 * ldo + n] = acc[j][0] + bv0;
            outF[row0 * ldo + n + 1] = acc[j][1] + bv1;
            outF[(row0 + 8) * ldo + n] = acc[j][2] + bv0;
            outF[(row0 + 8) * ldo + n + 1] = acc[j][3] + bv1;
        }
    } else if (mode == 2) {
#pragma unroll
        for (int j = 0; j < 4; ++j) {
            int n = n0 + 8 * j + c2;
            float bv0 = bias[n], bv1 = bias[n + 1];
            int b0r = 16 * w + r;
#pragma unroll
            for (int hh = 0; hh < 2; ++hh) {
                int bb = b0r + hh * 8;
                float v0 = tanhf(acc[j][2 * hh] + bv0);
                float v1 = tanhf(acc[j][2 * hh + 1] + bv1);
                outF[(size_t)bb * ldo + n] = v0;
                outF[(size_t)bb * ldo + n + 1] = v1;
                bf16 h0 = __float2bfloat16(v0);
                bf16 l0 = __float2bfloat16(v0 - __bfloat162float(h0));
                bf16 h1 = __float2bfloat16(v1);
                bf16 l1 = __float2bfloat16(v1 - __bfloat162float(h1));
                outHL[bb * 2048 + n] = h0;
                outHL[bb * 2048 + 1024 + n] = l0;
                outHL[bb * 2048 + n + 1] = h1;
                outHL[bb * 2048 + 1024 + n + 1] = l1;
            }
        }
    } else {
        float* Csm = (float*)smemA;  // alias: mainloop done
#pragma unroll
        for (int j = 0; j < 4; ++j) {
            int col = 8 * j + c2;
            float bv0 = bias[n0 + col], bv1 = bias[n0 + col + 1];
            Csm[(16 * w + r) * 33 + col] = acc[j][0] + bv0;
            Csm[(16 * w + r) * 33 + col + 1] = acc[j][1] + bv1;
            Csm[(16 * w + r + 8) * 33 + col] = acc[j][2] + bv0;
            Csm[(16 * w + r + 8) * 33 + col + 1] = acc[j][3] + bv1;
        }
        __syncthreads();
#pragma unroll
        for (int q = 0; q < 4; ++q) {
            int item = tid * 4 + q;   // 512 items = 64 b x 8 hu
            int b = item >> 3;
            int hu = item & 7;
            float gi = Csm[b * 33 + hu * 4 + 0];
            float gf = Csm[b * 33 + hu * 4 + 1];
            float gg = Csm[b * 33 + hu * 4 + 2];
            float go = Csm[b * 33 + hu * 4 + 3];
            int hg = (n0 >> 2) + hu;
            int idx = b * HDIM + hg;
            float cold = cstate[idx];
            float i_ = sigm(gi), f_ = sigm(gf), g_ = tanhf(gg), o_ = sigm(go);
            float cn = f_ * cold + i_ * g_;
            cstate[idx] = cn;
            float hv = o_ * tanhf(cn);
            if (outF) outF[idx] = hv;
            bf16 hi = __float2bfloat16(hv);
            bf16 lo = __float2bfloat16(hv - __bfloat162float(hi));
            outHL[b * 2048 + hg] = hi;
            outHL[b * 2048 + 1024 + hg] = lo;
        }
    }
}

// ---------------- fused attention: scores -> mask -> softmax -> context -> hi/lo ----------------
__global__ __launch_bounds__(256) void attn_k(const float* __restrict__ h2f,
                                              const int* __restrict__ masks,
                                              const float* __restrict__ encproj,
                                              const float* __restrict__ enc,
                                              bf16* __restrict__ athl) {
    const int b = blockIdx.x;
    __shared__ float sh2[HDIM];
    __shared__ float sred[LLEN];
    __shared__ float salpha[LLEN];
    __shared__ float stmp[LLEN];
    const int tid = threadIdx.x;
    const int w = tid >> 5, l = tid & 31;

    for (int k = tid; k < HDIM; k += 256) sh2[k] = h2f[b * HDIM + k];
    __syncthreads();

    // scores: warp w handles 16 l's
    for (int li = 0; li < 16; ++li) {
        int ll = w * 16 + li;
        const float* ep = encproj + ((size_t)(b * LLEN + ll)) * HDIM;
        float s = 0.f;
#pragma unroll 8
        for (int k = l; k < HDIM; k += 32) s += sh2[k] * ep[k];
#pragma unroll
        for (int o = 16; o; o >>= 1) s += __shfl_xor_sync(0xffffffffu, s, o);
        if (l == 0) sred[ll] = masks[b * LLEN + ll] ? -1e30f : s;
    }
    __syncthreads();

    // softmax over 128
    if (tid < 128) stmp[tid] = sred[tid];
    __syncthreads();
    for (int s = 64; s; s >>= 1) {
        if (tid < s) stmp[tid] = fmaxf(stmp[tid], stmp[tid + s]);
        __syncthreads();
    }
    const float mx = stmp[0];
    __syncthreads();
    if (tid < 128) {
        float p = __expf(sred[tid] - mx);
        salpha[tid] = p;
        stmp[tid] = p;
    }
    __syncthreads();
    for (int s = 64; s; s >>= 1) {
        if (tid < s) stmp[tid] += stmp[tid + s];
        __syncthreads();
    }
    const float inv = 1.f / stmp[0];
    __syncthreads();
    if (tid < 128) salpha[tid] *= inv;
    __syncthreads();

    // context: a_t[b, f..f+3] with f = tid*4
    float4 accv = make_float4(0.f, 0.f, 0.f, 0.f);
    const float4* ep4 = (const float4*)(enc + (size_t)b * LLEN * HEDIM);
#pragma unroll 4
    for (int ll = 0; ll < LLEN; ++ll) {
        float al = salpha[ll];
        float4 v = ep4[ll * 256 + tid];
        accv.x += al * v.x;
        accv.y += al * v.y;
        accv.z += al * v.z;
        accv.w += al * v.w;
    }
    int f = tid * 4;
    float vals[4] = {accv.x, accv.y, accv.z, accv.w};
#pragma unroll
    for (int i = 0; i < 4; ++i) {
        bf16 hi = __float2bfloat16(vals[i]);
        bf16 lo = __float2bfloat16(vals[i] - __bfloat162float(hi));
        athl[b * 2048 + f + i] = hi;
        athl[b * 2048 + 1024 + f + i] = lo;
    }
}

// ---------------- host launcher ----------------
extern "C" void kernel_launch(void* const* d_in, const int* in_sizes, int n_in,
                              void* d_out, int out_size) {
    const float* enc = (const float*)d_in[0];
    const int* masks = (const int*)d_in[1];
    const float* h1i = (const float*)d_in[2];
    const float* c1i = (const float*)d_in[3];
    const float* h2i = (const float*)d_in[4];
    const float* c2i = (const float*)d_in[5];
    const float* cap = (const float*)d_in[6];
    const float* W_ih1 = (const float*)d_in[7];
    const float* W_hh1 = (const float*)d_in[8];
    const float* b_ih1 = (const float*)d_in[9];
    const float* b_hh1 = (const float*)d_in[10];
    const float* W_ih2 = (const float*)d_in[11];
    const float* W_hh2 = (const float*)d_in[12];
    const float* b_ih2 = (const float*)d_in[13];
    const float* b_hh2 = (const float*)d_in[14];
    const float* W_att = (const float*)d_in[15];
    const float* b_att = (const float*)d_in[16];
    const float* W_comb = (const float*)d_in[17];
    const float* b_comb = (const float*)d_in[18];
    float* outs = (float*)d_out;  // (T, B, H)

    bf16 *pWih1, *pWhh1, *pWih2A, *pWih2B, *pWhh2, *pWcmA, *pWcmB, *pWatt;
    bf16 *pEnchl, *pCapshl, *pOhl, *pAthl;
    bf16 *pH1hl0, *pH2hl0;
    float *pEncproj, *pC1, *pC2, *pH2f, *pBg1, *pBg2;
    cudaGetSymbolAddress((void**)&pWih1, g_Wih1);
    cudaGetSymbolAddress((void**)&pWhh1, g_Whh1);
    cudaGetSymbolAddress((void**)&pWih2A, g_Wih2A);
    cudaGetSymbolAddress((void**)&pWih2B, g_Wih2B);
    cudaGetSymbolAddress((void**)&pWhh2, g_Whh2);
    cudaGetSymbolAddress((void**)&pWcmA, g_WcmA);
    cudaGetSymbolAddress((void**)&pWcmB, g_WcmB);
    cudaGetSymbolAddress((void**)&pWatt, g_Watt);
    cudaGetSymbolAddress((void**)&pEnchl, g_enchl);
    cudaGetSymbolAddress((void**)&pCapshl, g_capshl);
    cudaGetSymbolAddress((void**)&pEncproj, g_encproj);
    cudaGetSymbolAddress((void**)&pH1hl0, g_h1hl);
    cudaGetSymbolAddress((void**)&pH2hl0, g_h2hl);
    cudaGetSymbolAddress((void**)&pOhl, g_ohl);
    cudaGetSymbolAddress((void**)&pAthl, g_athl);
    cudaGetSymbolAddress((void**)&pC1, g_c1);
    cudaGetSymbolAddress((void**)&pC2, g_c2);
    cudaGetSymbolAddress((void**)&pH2f, g_h2f);
    cudaGetSymbolAddress((void**)&pBg1, g_bg1);
    cudaGetSymbolAddress((void**)&pBg2, g_bg2);

    bf16* pH1hl[2] = {pH1hl0, pH1hl0 + BBATCH * 2048};
    bf16* pH2hl[2] = {pH2hl0, pH2hl0 + BBATCH * 2048};

    // ---- prologue: conversions ----
    auto cgrid = [](int n) { return (n + 255) / 256; };
    conv_whl<<<cgrid(4096 * 512), 256>>>(W_ih1, 512, 0, 512, pWih1, 1, 4096);
    conv_whl<<<cgrid(4096 * 1024), 256>>>(W_hh1, 1024, 0, 1024, pWhh1, 1, 4096);
    conv_whl<<<cgrid(4096 * 1024), 256>>>(W_ih2, 2048, 0, 1024, pWih2A, 1, 4096);
    conv_whl<<<cgrid(4096 * 1024), 256>>>(W_ih2, 2048, 1024, 1024, pWih2B, 1, 4096);
    conv_whl<<<cgrid(4096 * 1024), 256>>>(W_hh2, 1024, 0, 1024, pWhh2, 1, 4096);
    conv_whl<<<cgrid(1024 * 1024), 256>>>(W_comb, 2048, 0, 1024, pWcmA, 0, 1024);
    conv_whl<<<cgrid(1024 * 1024), 256>>>(W_comb, 2048, 1024, 1024, pWcmB, 0, 1024);
    conv_whl<<<cgrid(1024 * 1024), 256>>>(W_att, 1024, 0, 1024, pWatt, 0, 1024);
    conv_whl<<<cgrid(8192 * 1024), 256>>>(enc, 1024, 0, 1024, pEnchl, 0, 8192);
    conv_whl<<<cgrid(3072 * 512), 256>>>(cap, 512, 0, 512, pCapshl, 0, 3072);
    conv_bias<<<16, 256>>>(b_ih1, b_hh1, b_ih2, b_hh2);
    init_k<<<(BBATCH * HDIM + 255) / 256, 256>>>(h1i, c1i, h2i, c2i);

    // enc_proj = enc @ W_att^T + b_att  (M=8192, N=1024)
    mma_gemm<<<dim3(32, 128), 128>>>(
        pEnchl, pWatt, 1024,
        nullptr, nullptr, 0,
        nullptr, nullptr, 0,
        1, b_att, pEncproj, 1024, nullptr, nullptr, 0);

    // ---- time loop ----
    for (int t = 0; t < TSTEPS; ++t) {
        const int cur = t & 1;
        const bf16* capst = pCapshl + (size_t)t * BBATCH * 1024;

        // LSTM1: gates = x@Wih1^T + h1@Whh1^T + b ; epilogue -> h1hl[cur^1], c1
        mma_gemm<<<dim3(128, 1), 128>>>(
            capst, pWih1, 512,
            pH1hl[cur], pWhh1, 1024,
            nullptr, nullptr, 0,
            2, pBg1, nullptr, 0, pH1hl[cur ^ 1], pC1, 1);

        // LSTM2: gates = h1@WihA + o_prev@WihB + h2@Whh2 + b ; -> h2hl[cur^1], c2, h2f
        mma_gemm<<<dim3(128, 1), 128>>>(
            pH1hl[cur ^ 1], pWih2A, 1024,
            pOhl, pWih2B, 1024,
            pH2hl[cur], pWhh2, 1024,
            3, pBg2, pH2f, 0, pH2hl[cur ^ 1], pC2, 1);

        // attention (fused scores/softmax/context) -> athl
        attn_k<<<BBATCH, 256>>>(pH2f, masks, pEncproj, enc, pAthl);

        // o_t = tanh(a_t@WcmA + h2@WcmB + b) -> outs[t], ohl
        mma_gemm<<<dim3(32, 1), 128>>>(
            pAthl, pWcmA, 1024,
            pH2hl[cur ^ 1], pWcmB, 1024,
            nullptr, nullptr, 0,
            2, b_comb, outs + (size_t)t * BBATCH * HDIM, 1024, pOhl, nullptr, 2);
    }
}

// round 3
// speedup vs baseline: 1.9892x; 1.9892x over previous
#include <cuda_runtime.h>
#include <cuda_bf16.h>
#include <math.h>
#include <stdint.h>

#define BBATCH 64
#define LLEN 128
#define TSTEPS 48
#define EDIM 512
#define HEDIM 1024
#define HDIM 1024

typedef __nv_bfloat16 bf16;

// ---------------- device scratch ----------------
__device__ bf16 g_Wih1[4096 * 1024];      // [4096][2*512] hi|lo, gate-interleaved rows
__device__ bf16 g_Whh1[4096 * 2048];
__device__ bf16 g_Wih2A[4096 * 2048];
__device__ bf16 g_Wih2B[4096 * 2048];
__device__ bf16 g_Whh2[4096 * 2048];
__device__ bf16 g_WcmA[1024 * 2048];
__device__ bf16 g_WcmB[1024 * 2048];
__device__ bf16 g_Watt[1024 * 2048];
__device__ bf16 g_enchl[8192 * 2048];
__device__ bf16 g_capshl[3072 * 1024];
__device__ float g_encproj[8192 * 1024];  // fp32
__device__ float g_pregates[3072 * 4096]; // x@Wih1^T + b, all 48 steps  (48 MB)
__device__ bf16 g_h1hl[2][BBATCH * 2048];
__device__ bf16 g_h2hl[2][BBATCH * 2048];
__device__ bf16 g_ohl[BBATCH * 2048];
__device__ bf16 g_athl[BBATCH * 2048];
__device__ float g_c1[BBATCH * HDIM];
__device__ float g_c2[BBATCH * HDIM];
__device__ float g_h2f[BBATCH * HDIM];
__device__ float g_bg1[4096];
__device__ float g_bg2[4096];

__device__ __forceinline__ float sigm(float x) { return 1.f / (1.f + __expf(-x)); }

#define CP16(dst, src) \
    asm volatile("cp.async.cg.shared.global [%0], [%1], 16;\n" ::"r"(dst), "l"(src))
#define LDSM4(R0, R1, R2, R3, ADDR)                                        \
    asm volatile("ldmatrix.sync.aligned.m8n8.x4.shared.b16 {%0,%1,%2,%3},[%4];\n" \
                 : "=r"(R0), "=r"(R1), "=r"(R2), "=r"(R3)                  \
                 : "r"(ADDR))
#define MMA16816(C, A0, A1, A2, A3, B0, B1)                                    \
    asm volatile(                                                               \
        "mma.sync.aligned.m16n8k16.row.col.f32.bf16.bf16.f32 "                  \
        "{%0,%1,%2,%3},{%4,%5,%6,%7},{%8,%9},{%0,%1,%2,%3};\n"                  \
        : "+f"((C)[0]), "+f"((C)[1]), "+f"((C)[2]), "+f"((C)[3])                \
        : "r"(A0), "r"(A1), "r"(A2), "r"(A3), "r"(B0), "r"(B1))

// ---------------- conversions ----------------
__global__ void conv_whl(const float* __restrict__ src, int srcld, int colOff, int K,
                         bf16* __restrict__ dst, int interleave, int N) {
    int idx = blockIdx.x * 256 + threadIdx.x;
    if (idx >= N * K) return;
    int n = idx / K, k = idx - n * K;
    int srcn = interleave ? ((n & 3) * HDIM + (n >> 2)) : n;
    float v = src[(size_t)srcn * srcld + colOff + k];
    bf16 hi = __float2bfloat16(v);
    bf16 lo = __float2bfloat16(v - __bfloat162float(hi));
    dst[(size_t)n * 2 * K + k] = hi;
    dst[(size_t)n * 2 * K + K + k] = lo;
}

__global__ void conv_bias(const float* __restrict__ bi1, const float* __restrict__ bh1,
                          const float* __restrict__ bi2, const float* __restrict__ bh2) {
    int n = blockIdx.x * 256 + threadIdx.x;
    if (n >= 4096) return;
    int srcn = (n & 3) * HDIM + (n >> 2);
    g_bg1[n] = bi1[srcn] + bh1[srcn];
    g_bg2[n] = bi2[srcn] + bh2[srcn];
}

__global__ void init_k(const float* __restrict__ h1i, const float* __restrict__ c1i,
                       const float* __restrict__ h2i, const float* __restrict__ c2i) {
    int i = blockIdx.x * 256 + threadIdx.x;
    if (i >= BBATCH * HDIM) return;
    int b = i >> 10, k = i & 1023;
    g_c1[i] = c1i[i];
    g_c2[i] = c2i[i];
    g_h2f[i] = h2i[i];
    float v1 = h1i[i];
    bf16 h = __float2bfloat16(v1);
    bf16 l = __float2bfloat16(v1 - __bfloat162float(h));
    g_h1hl[0][b * 2048 + k] = h;
    g_h1hl[0][b * 2048 + 1024 + k] = l;
    float v2 = h2i[i];
    h = __float2bfloat16(v2);
    l = __float2bfloat16(v2 - __bfloat162float(h));
    g_h2hl[0][b * 2048 + k] = h;
    g_h2hl[0][b * 2048 + 1024 + k] = l;
    bf16 z = __float2bfloat16(0.f);
    g_ohl[b * 2048 + k] = z;
    g_ohl[b * 2048 + 1024 + k] = z;
}

// ---------------- merged 3-term compensated bf16 GEMM ----------------
// Per 64-K chunk: load Ahi|Alo (64x64 each), Whi|Wlo (32x64 each) once; acc +=
// Ahi*Whi + Ahi*Wlo + Alo*Whi. 4-stage cp.async pipeline.
// Stage layout (24576 B): [Ahi 8192][Alo 8192][Whi 4096][Wlo 4096]
#define STGB 24576
#define NSTG 4

__global__ __launch_bounds__(128) void mma3(
    const bf16* A0, const bf16* W0, int K0,
    const bf16* A1, const bf16* W1, int K1,
    const bf16* A2, const bf16* W2, int K2,
    int npairs,
    const float* __restrict__ biasV,
    const float* __restrict__ biasM,   // per-(m,n) bias matrix (ld 4096), overrides biasV
    float* __restrict__ outF, int ldo,
    bf16* __restrict__ outHL,
    float* __restrict__ cstate,
    int mode) {
    extern __shared__ __align__(16) char smem[];

    const int tid = threadIdx.x;
    const int w = tid >> 5;
    const int l = tid & 31;
    const int m0 = blockIdx.y * 64;
    const int n0 = blockIdx.x * 32;

    const bf16* Ab[3] = {A0, A1, A2};
    const bf16* Wb[3] = {W0, W1, W2};
    const int Kp[3] = {K0, K1, K2};

    int NCH = 0;
    for (int p = 0; p < npairs; ++p) NCH += Kp[p] >> 6;

    const uint32_t sB = (uint32_t)__cvta_generic_to_shared(smem);

    int cp = 0, ckt = 0;
    auto issue = [&](int stg) {
        const bf16* A = Ab[cp];
        const bf16* W = Wb[cp];
        const int K = Kp[cp];
        const int ld = K << 1;
        const uint32_t base = sB + stg * STGB;
#pragma unroll
        for (int i = 0; i < 12; ++i) {
            int c = tid + (i << 7);  // 0..1535
            if (c < 512) {            // Ahi
                int row = c >> 3, ch = c & 7;
                const bf16* src = A + (size_t)(m0 + row) * ld + ckt + (ch << 3);
                CP16(base + row * 128 + ((ch ^ (row & 7)) << 4), src);
            } else if (c < 1024) {    // Alo
                int c2 = c - 512;
                int row = c2 >> 3, ch = c2 & 7;
                const bf16* src = A + (size_t)(m0 + row) * ld + K + ckt + (ch << 3);
                CP16(base + 8192 + row * 128 + ((ch ^ (row & 7)) << 4), src);
            } else if (c < 1280) {    // Whi
                int c2 = c - 1024;
                int row = c2 >> 3, ch = c2 & 7;
                const bf16* src = W + (size_t)(n0 + row) * ld + ckt + (ch << 3);
                CP16(base + 16384 + row * 128 + ((ch ^ (row & 7)) << 4), src);
            } else {                  // Wlo
                int c2 = c - 1280;
                int row = c2 >> 3, ch = c2 & 7;
                const bf16* src = W + (size_t)(n0 + row) * ld + K + ckt + (ch << 3);
                CP16(base + 20480 + row * 128 + ((ch ^ (row & 7)) << 4), src);
            }
        }
        asm volatile("cp.async.commit_group;\n" ::);
        ckt += 64;
        if (ckt >= K) { ckt = 0; ++cp; }
    };

    float acc[4][4];
#pragma unroll
    for (int j = 0; j < 4; ++j)
#pragma unroll
        for (int i = 0; i < 4; ++i) acc[j][i] = 0.f;

    const int npre = (NCH < NSTG - 1) ? NCH : (NSTG - 1);
    for (int i = 0; i < npre; ++i) issue(i);

    const int arow = 16 * w + (l & 15);
    const int asel = (l >> 4) & 1;
    const int nrow0 = (l & 7) + ((l & 16) >> 1);
    const int nrow1 = nrow0 + 16;
    const int bsel = (l >> 3) & 1;

    for (int it = 0; it < NCH; ++it) {
        const int pend = ((NCH < it + NSTG - 1) ? NCH : (it + NSTG - 1)) - (it + 1);
        if (pend >= 2)      asm volatile("cp.async.wait_group 2;\n" ::);
        else if (pend == 1) asm volatile("cp.async.wait_group 1;\n" ::);
        else                asm volatile("cp.async.wait_group 0;\n" ::);
        __syncthreads();
        if (it + NSTG - 1 < NCH) issue((it + NSTG - 1) & (NSTG - 1));

        const uint32_t aHi = sB + (it & (NSTG - 1)) * STGB;
        const uint32_t aLo = aHi + 8192;
        const uint32_t wHi = aHi + 16384;
        const uint32_t wLo = aHi + 20480;
#pragma unroll
        for (int kh = 0; kh < 4; ++kh) {
            const int ac = 2 * kh + asel;
            const int bc = 2 * kh + bsel;
            const uint32_t aoff = arow * 128 + ((ac ^ (arow & 7)) << 4);
            const uint32_t boff0 = nrow0 * 128 + ((bc ^ (nrow0 & 7)) << 4);
            const uint32_t boff1 = nrow1 * 128 + ((bc ^ (nrow1 & 7)) << 4);
            uint32_t ah0, ah1, ah2, ah3, al0, al1, al2, al3;
            LDSM4(ah0, ah1, ah2, ah3, aHi + aoff);
            LDSM4(al0, al1, al2, al3, aLo + aoff);
            uint32_t bh0, bh1, bh2, bh3, bh4, bh5, bh6, bh7;
            LDSM4(bh0, bh1, bh2, bh3, wHi + boff0);
            LDSM4(bh4, bh5, bh6, bh7, wHi + boff1);
            uint32_t bl0, bl1, bl2, bl3, bl4, bl5, bl6, bl7;
            LDSM4(bl0, bl1, bl2, bl3, wLo + boff0);
            LDSM4(bl4, bl5, bl6, bl7, wLo + boff1);
            MMA16816(acc[0], ah0, ah1, ah2, ah3, bh0, bh1);
            MMA16816(acc[1], ah0, ah1, ah2, ah3, bh2, bh3);
            MMA16816(acc[2], ah0, ah1, ah2, ah3, bh4, bh5);
            MMA16816(acc[3], ah0, ah1, ah2, ah3, bh6, bh7);
            MMA16816(acc[0], ah0, ah1, ah2, ah3, bl0, bl1);
            MMA16816(acc[1], ah0, ah1, ah2, ah3, bl2, bl3);
            MMA16816(acc[2], ah0, ah1, ah2, ah3, bl4, bl5);
            MMA16816(acc[3], ah0, ah1, ah2, ah3, bl6, bl7);
            MMA16816(acc[0], al0, al1, al2, al3, bh0, bh1);
            MMA16816(acc[1], al0, al1, al2, al3, bh2, bh3);
            MMA16816(acc[2], al0, al1, al2, al3, bh4, bh5);
            MMA16816(acc[3], al0, al1, al2, al3, bh6, bh7);
        }
    }
    __syncthreads();

    const int r = l >> 2;
    const int c2 = (l & 3) * 2;

    if (mode == 0) {
#pragma unroll
        for (int j = 0; j < 4; ++j) {
            int n = n0 + 8 * j + c2;
            float bv0 = biasV[n], bv1 = biasV[n + 1];
            size_t row0 = (size_t)(m0 + 16 * w + r);
            outF[row0 * ldo + n] = acc[j][0] + bv0;
            outF[row0 * ldo + n + 1] = acc[j][1] + bv1;
            outF[(row0 + 8) * ldo + n] = acc[j][2] + bv0;
            outF[(row0 + 8) * ldo + n + 1] = acc[j][3] + bv1;
        }
    } else if (mode == 2) {
#pragma unroll
        for (int j = 0; j < 4; ++j) {
            int n = n0 + 8 * j + c2;
            float bv0 = biasV[n], bv1 = biasV[n + 1];
            int b0r = 16 * w + r;
#pragma unroll
            for (int hh = 0; hh < 2; ++hh) {
                int bb = b0r + hh * 8;
                float v0 = tanhf(acc[j][2 * hh] + bv0);
                float v1 = tanhf(acc[j][2 * hh + 1] + bv1);
                outF[(size_t)bb * ldo + n] = v0;
                outF[(size_t)bb * ldo + n + 1] = v1;
                bf16 h0 = __float2bfloat16(v0);
                bf16 l0 = __float2bfloat16(v0 - __bfloat162float(h0));
                bf16 h1 = __float2bfloat16(v1);
                bf16 l1 = __float2bfloat16(v1 - __bfloat162float(h1));
                outHL[bb * 2048 + n] = h0;
                outHL[bb * 2048 + 1024 + n] = l0;
                outHL[bb * 2048 + n + 1] = h1;
                outHL[bb * 2048 + 1024 + n + 1] = l1;
            }
        }
    } else {
        float* Csm = (float*)smem;
#pragma unroll
        for (int j = 0; j < 4; ++j) {
            int col = 8 * j + c2;
            int n = n0 + col;
#pragma unroll
            for (int hh = 0; hh < 2; ++hh) {
                int m = 16 * w + r + hh * 8;
                float b0 = biasM ? biasM[(size_t)m * 4096 + n] : biasV[n];
                float b1 = biasM ? biasM[(size_t)m * 4096 + n + 1] : biasV[n + 1];
                Csm[m * 33 + col] = acc[j][2 * hh] + b0;
                Csm[m * 33 + col + 1] = acc[j][2 * hh + 1] + b1;
            }
        }
        __syncthreads();
#pragma unroll
        for (int q = 0; q < 4; ++q) {
            int item = tid * 4 + q;  // 512 = 64 b x 8 hu
            int b = item >> 3;
            int hu = item & 7;
            float gi = Csm[b * 33 + hu * 4 + 0];
            float gf = Csm[b * 33 + hu * 4 + 1];
            float gg = Csm[b * 33 + hu * 4 + 2];
            float go = Csm[b * 33 + hu * 4 + 3];
            int hg = (n0 >> 2) + hu;
            int idx = b * HDIM + hg;
            float cold = cstate[idx];
            float i_ = sigm(gi), f_ = sigm(gf), g_ = tanhf(gg), o_ = sigm(go);
            float cn = f_ * cold + i_ * g_;
            cstate[idx] = cn;
            float hv = o_ * tanhf(cn);
            if (outF) outF[idx] = hv;
            bf16 hi = __float2bfloat16(hv);
            bf16 lo = __float2bfloat16(hv - __bfloat162float(hi));
            outHL[b * 2048 + hg] = hi;
            outHL[b * 2048 + 1024 + hg] = lo;
        }
    }
}

// ---------------- fused attention ----------------
__global__ __launch_bounds__(256) void attn_k(const float* __restrict__ h2f,
                                              const int* __restrict__ masks,
                                              const float* __restrict__ encproj,
                                              const float* __restrict__ enc,
                                              bf16* __restrict__ athl) {
    const int b = blockIdx.x;
    __shared__ __align__(16) float sh2[HDIM];
    __shared__ float sred[LLEN];
    __shared__ float salpha[LLEN];
    __shared__ float stmp[LLEN];
    const int tid = threadIdx.x;
    const int w = tid >> 5, l = tid & 31;

    {
        const float4* src = (const float4*)(h2f + b * HDIM);
        float4* dst = (float4*)sh2;
        if (tid < 256) dst[tid] = src[tid];
    }
    __syncthreads();

    const float4* sh4 = (const float4*)sh2;
    for (int li = 0; li < 16; ++li) {
        int ll = w * 16 + li;
        const float4* ep4 = (const float4*)(encproj + ((size_t)(b * LLEN + ll)) * HDIM);
        float s = 0.f;
#pragma unroll
        for (int j = 0; j < 8; ++j) {
            float4 hv = sh4[l + 32 * j];
            float4 ev = ep4[l + 32 * j];
            s += hv.x * ev.x + hv.y * ev.y + hv.z * ev.z + hv.w * ev.w;
        }
#pragma unroll
        for (int o = 16; o; o >>= 1) s += __shfl_xor_sync(0xffffffffu, s, o);
        if (l == 0) sred[ll] = masks[b * LLEN + ll] ? -1e30f : s;
    }
    __syncthreads();

    if (tid < 128) stmp[tid] = sred[tid];
    __syncthreads();
    for (int s = 64; s; s >>= 1) {
        if (tid < s) stmp[tid] = fmaxf(stmp[tid], stmp[tid + s]);
        __syncthreads();
    }
    const float mx = stmp[0];
    __syncthreads();
    if (tid < 128) {
        float p = __expf(sred[tid] - mx);
        salpha[tid] = p;
        stmp[tid] = p;
    }
    __syncthreads();
    for (int s = 64; s; s >>= 1) {
        if (tid < s) stmp[tid] += stmp[tid + s];
        __syncthreads();
    }
    const float inv = 1.f / stmp[0];
    __syncthreads();
    if (tid < 128) salpha[tid] *= inv;
    __syncthreads();

    // context with 8 independent partial accumulators (MLP)
    float4 p[8];
#pragma unroll
    for (int u = 0; u < 8; ++u) p[u] = make_float4(0.f, 0.f, 0.f, 0.f);
    const float4* ep4 = (const float4*)(enc + (size_t)b * LLEN * HEDIM);
    for (int l0 = 0; l0 < LLEN; l0 += 8) {
#pragma unroll
        for (int u = 0; u < 8; ++u) {
            float al = salpha[l0 + u];
            float4 v = ep4[(l0 + u) * 256 + tid];
            p[u].x += al * v.x;
            p[u].y += al * v.y;
            p[u].z += al * v.z;
            p[u].w += al * v.w;
        }
    }
#pragma unroll
    for (int u = 1; u < 8; ++u) {
        p[0].x += p[u].x; p[0].y += p[u].y; p[0].z += p[u].z; p[0].w += p[u].w;
    }
    int f = tid * 4;
    float vals[4] = {p[0].x, p[0].y, p[0].z, p[0].w};
#pragma unroll
    for (int i = 0; i < 4; ++i) {
        bf16 hi = __float2bfloat16(vals[i]);
        bf16 lo = __float2bfloat16(vals[i] - __bfloat162float(hi));
        athl[b * 2048 + f + i] = hi;
        athl[b * 2048 + 1024 + f + i] = lo;
    }
}

// ---------------- host launcher ----------------
extern "C" void kernel_launch(void* const* d_in, const int* in_sizes, int n_in,
                              void* d_out, int out_size) {
    const float* enc = (const float*)d_in[0];
    const int* masks = (const int*)d_in[1];
    const float* h1i = (const float*)d_in[2];
    const float* c1i = (const float*)d_in[3];
    const float* h2i = (const float*)d_in[4];
    const float* c2i = (const float*)d_in[5];
    const float* cap = (const float*)d_in[6];
    const float* W_ih1 = (const float*)d_in[7];
    const float* W_hh1 = (const float*)d_in[8];
    const float* b_ih1 = (const float*)d_in[9];
    const float* b_hh1 = (const float*)d_in[10];
    const float* W_ih2 = (const float*)d_in[11];
    const float* W_hh2 = (const float*)d_in[12];
    const float* b_ih2 = (const float*)d_in[13];
    const float* b_hh2 = (const float*)d_in[14];
    const float* W_att = (const float*)d_in[15];
    const float* b_att = (const float*)d_in[16];
    const float* W_comb = (const float*)d_in[17];
    const float* b_comb = (const float*)d_in[18];
    float* outs = (float*)d_out;

    bf16 *pWih1, *pWhh1, *pWih2A, *pWih2B, *pWhh2, *pWcmA, *pWcmB, *pWatt;
    bf16 *pEnchl, *pCapshl, *pOhl, *pAthl, *pH1hl0, *pH2hl0;
    float *pEncproj, *pPre, *pC1, *pC2, *pH2f, *pBg1, *pBg2;
    cudaGetSymbolAddress((void**)&pWih1, g_Wih1);
    cudaGetSymbolAddress((void**)&pWhh1, g_Whh1);
    cudaGetSymbolAddress((void**)&pWih2A, g_Wih2A);
    cudaGetSymbolAddress((void**)&pWih2B, g_Wih2B);
    cudaGetSymbolAddress((void**)&pWhh2, g_Whh2);
    cudaGetSymbolAddress((void**)&pWcmA, g_WcmA);
    cudaGetSymbolAddress((void**)&pWcmB, g_WcmB);
    cudaGetSymbolAddress((void**)&pWatt, g_Watt);
    cudaGetSymbolAddress((void**)&pEnchl, g_enchl);
    cudaGetSymbolAddress((void**)&pCapshl, g_capshl);
    cudaGetSymbolAddress((void**)&pEncproj, g_encproj);
    cudaGetSymbolAddress((void**)&pPre, g_pregates);
    cudaGetSymbolAddress((void**)&pH1hl0, g_h1hl);
    cudaGetSymbolAddress((void**)&pH2hl0, g_h2hl);
    cudaGetSymbolAddress((void**)&pOhl, g_ohl);
    cudaGetSymbolAddress((void**)&pAthl, g_athl);
    cudaGetSymbolAddress((void**)&pC1, g_c1);
    cudaGetSymbolAddress((void**)&pC2, g_c2);
    cudaGetSymbolAddress((void**)&pH2f, g_h2f);
    cudaGetSymbolAddress((void**)&pBg1, g_bg1);
    cudaGetSymbolAddress((void**)&pBg2, g_bg2);

    bf16* pH1hl[2] = {pH1hl0, pH1hl0 + BBATCH * 2048};
    bf16* pH2hl[2] = {pH2hl0, pH2hl0 + BBATCH * 2048};

    static int smem_set = 0;
    if (!smem_set) {
        cudaFuncSetAttribute(mma3, cudaFuncAttributeMaxDynamicSharedMemorySize,
                             NSTG * STGB);
        smem_set = 1;
    }
    const int SMEM = NSTG * STGB;

    auto cgrid = [](int n) { return (n + 255) / 256; };
    conv_whl<<<cgrid(4096 * 512), 256>>>(W_ih1, 512, 0, 512, pWih1, 1, 4096);
    conv_whl<<<cgrid(4096 * 1024), 256>>>(W_hh1, 1024, 0, 1024, pWhh1, 1, 4096);
    conv_whl<<<cgrid(4096 * 1024), 256>>>(W_ih2, 2048, 0, 1024, pWih2A, 1, 4096);
    conv_whl<<<cgrid(4096 * 1024), 256>>>(W_ih2, 2048, 1024, 1024, pWih2B, 1, 4096);
    conv_whl<<<cgrid(4096 * 1024), 256>>>(W_hh2, 1024, 0, 1024, pWhh2, 1, 4096);
    conv_whl<<<cgrid(1024 * 1024), 256>>>(W_comb, 2048, 0, 1024, pWcmA, 0, 1024);
    conv_whl<<<cgrid(1024 * 1024), 256>>>(W_comb, 2048, 1024, 1024, pWcmB, 0, 1024);
    conv_whl<<<cgrid(1024 * 1024), 256>>>(W_att, 1024, 0, 1024, pWatt, 0, 1024);
    conv_whl<<<cgrid(8192 * 1024), 256>>>(enc, 1024, 0, 1024, pEnchl, 0, 8192);
    conv_whl<<<cgrid(3072 * 512), 256>>>(cap, 512, 0, 512, pCapshl, 0, 3072);
    conv_bias<<<16, 256>>>(b_ih1, b_hh1, b_ih2, b_hh2);
    init_k<<<(BBATCH * HDIM + 255) / 256, 256>>>(h1i, c1i, h2i, c2i);

    // pregates1 = captions_all @ Wih1^T + bg1  (M=3072, N=4096)
    mma3<<<dim3(128, 48), 128, SMEM>>>(
        pCapshl, pWih1, 512, nullptr, nullptr, 0, nullptr, nullptr, 0,
        1, pBg1, nullptr, pPre, 4096, nullptr, nullptr, 0);

    // enc_proj = enc @ W_att^T + b_att  (M=8192, N=1024)
    mma3<<<dim3(32, 128), 128, SMEM>>>(
        pEnchl, pWatt, 1024, nullptr, nullptr, 0, nullptr, nullptr, 0,
        1, b_att, nullptr, pEncproj, 1024, nullptr, nullptr, 0);

    for (int t = 0; t < TSTEPS; ++t) {
        const int cur = t & 1;

        // LSTM1: acc = h1@Whh1^T ; bias = pregates[t] ; epilogue -> h1hl[nxt], c1
        mma3<<<dim3(128, 1), 128, SMEM>>>(
            pH1hl[cur], pWhh1, 1024, nullptr, nullptr, 0, nullptr, nullptr, 0,
            1, nullptr, pPre + (size_t)t * BBATCH * 4096,
            nullptr, 0, pH1hl[cur ^ 1], pC1, 1);

        // LSTM2
        mma3<<<dim3(128, 1), 128, SMEM>>>(
            pH1hl[cur ^ 1], pWih2A, 1024, pOhl, pWih2B, 1024, pH2hl[cur], pWhh2, 1024,
            3, pBg2, nullptr, pH2f, 0, pH2hl[cur ^ 1], pC2, 1);

        attn_k<<<BBATCH, 256>>>(pH2f, masks, pEncproj, enc, pAthl);

        // o_t = tanh(a@WcmA + h2@WcmB + b)
        mma3<<<dim3(32, 1), 128, SMEM>>>(
            pAthl, pWcmA, 1024, pH2hl[cur ^ 1], pWcmB, 1024, nullptr, nullptr, 0,
            2, b_comb, nullptr, outs + (size_t)t * BBATCH * HDIM, 1024, pOhl, nullptr, 2);
    }
}